// round 3
// baseline (speedup 1.0000x reference)
#include <cuda_runtime.h>

#define N_NODES 40000
#define N_EDGES 640000
#define HID     128
#define NG      50

// Scratch (device globals: allocation-free per harness rules)
__device__ float g_x[N_NODES * HID];    // atom_net output
__device__ float g_agg[N_NODES * HID];  // scatter-add accumulator

__device__ __forceinline__ float silu_f(float v) {
    return v / (1.0f + __expf(-v));
}

// Register-tiled GEMM fragment: each thread computes 4 rows x 8 cols.
// a_s: [rows][AS] smem, w_s: [K][128] smem, reduction over K.
template<int K, int AS>
__device__ __forceinline__ void gemm_tile(const float* __restrict__ a_s,
                                          const float* __restrict__ w_s,
                                          int r0, int j0, float acc[4][8])
{
    #pragma unroll
    for (int i = 0; i < 4; i++)
        #pragma unroll
        for (int j = 0; j < 8; j++) acc[i][j] = 0.0f;

    #pragma unroll 2
    for (int k = 0; k < K; ++k) {
        const float4 w0 = *(const float4*)(w_s + k * 128 + j0);
        const float4 w1 = *(const float4*)(w_s + k * 128 + j0 + 4);
        float av[4];
        #pragma unroll
        for (int i = 0; i < 4; i++) av[i] = a_s[(r0 + i) * AS + k];
        #pragma unroll
        for (int i = 0; i < 4; i++) {
            acc[i][0] += av[i] * w0.x; acc[i][1] += av[i] * w0.y;
            acc[i][2] += av[i] * w0.z; acc[i][3] += av[i] * w0.w;
            acc[i][4] += av[i] * w1.x; acc[i][5] += av[i] * w1.y;
            acc[i][6] += av[i] * w1.z; acc[i][7] += av[i] * w1.w;
        }
    }
}

// Fused 2-layer node MLP over 64-node tiles.
// mode 0: in = in_p (h), out = g_x, zero g_agg rows.
// mode 1: in = g_agg,    out = out_p, add resid_p (h).
__global__ __launch_bounds__(256) void node_mlp_kernel(
    int mode,
    const float* __restrict__ in_p,
    const float* __restrict__ w1, const float* __restrict__ b1,
    const float* __restrict__ w2, const float* __restrict__ b2,
    float* __restrict__ out_p,
    const float* __restrict__ resid_p)
{
    extern __shared__ float sm[];
    float* w_s = sm;                 // 128*128
    float* a_s = sm + 128 * 128;     // 64*132
    float* m_s = a_s + 64 * 132;     // 64*132

    const int tid = threadIdx.x;
    const int tx = tid & 15, ty = tid >> 4;
    const int j0 = tx * 8, r0 = ty * 4;
    const int node0 = blockIdx.x * 64;

    const float* in  = (mode == 0) ? in_p : g_agg;
    float*       out = (mode == 0) ? g_x  : out_p;

    for (int i = tid; i < 64 * 128; i += 256)
        a_s[(i >> 7) * 132 + (i & 127)] = in[node0 * 128 + i];
    for (int i = tid; i < 128 * 128; i += 256) w_s[i] = w1[i];
    __syncthreads();

    const float4 b1A = *(const float4*)(b1 + j0);
    const float4 b1B = *(const float4*)(b1 + j0 + 4);

    float acc[4][8];
    gemm_tile<128, 132>(a_s, w_s, r0, j0, acc);

    #pragma unroll
    for (int i = 0; i < 4; i++) {
        float4 v0, v1;
        v0.x = silu_f(acc[i][0] + b1A.x); v0.y = silu_f(acc[i][1] + b1A.y);
        v0.z = silu_f(acc[i][2] + b1A.z); v0.w = silu_f(acc[i][3] + b1A.w);
        v1.x = silu_f(acc[i][4] + b1B.x); v1.y = silu_f(acc[i][5] + b1B.y);
        v1.z = silu_f(acc[i][6] + b1B.z); v1.w = silu_f(acc[i][7] + b1B.w);
        *(float4*)(m_s + (r0 + i) * 132 + j0) = v0;
        *(float4*)(m_s + (r0 + i) * 132 + j0 + 4) = v1;
    }
    __syncthreads();                       // all GEMM1 reads of w_s done
    for (int i = tid; i < 128 * 128; i += 256) w_s[i] = w2[i];
    __syncthreads();

    const float4 b2A = *(const float4*)(b2 + j0);
    const float4 b2B = *(const float4*)(b2 + j0 + 4);

    gemm_tile<128, 132>(m_s, w_s, r0, j0, acc);

    #pragma unroll
    for (int i = 0; i < 4; i++) {
        const int g = node0 + r0 + i;
        float4 o0, o1;
        o0.x = acc[i][0] + b2A.x; o0.y = acc[i][1] + b2A.y;
        o0.z = acc[i][2] + b2A.z; o0.w = acc[i][3] + b2A.w;
        o1.x = acc[i][4] + b2B.x; o1.y = acc[i][5] + b2B.y;
        o1.z = acc[i][6] + b2B.z; o1.w = acc[i][7] + b2B.w;
        if (mode == 1) {
            const float4 h0 = *(const float4*)(resid_p + g * 128 + j0);
            const float4 h1 = *(const float4*)(resid_p + g * 128 + j0 + 4);
            o0.x += h0.x; o0.y += h0.y; o0.z += h0.z; o0.w += h0.w;
            o1.x += h1.x; o1.y += h1.y; o1.z += h1.z; o1.w += h1.w;
        }
        *(float4*)(out + g * 128 + j0) = o0;
        *(float4*)(out + g * 128 + j0 + 4) = o1;
        if (mode == 0) {
            const float4 z = make_float4(0.f, 0.f, 0.f, 0.f);
            *(float4*)(g_agg + g * 128 + j0) = z;
            *(float4*)(g_agg + g * 128 + j0 + 4) = z;
        }
    }
}

// Persistent edge kernel: filter_net (2-layer MLP on dist_feat) fused with
// message = W * x[src] and scatter-add into g_agg[dst] (vector atomics).
__global__ __launch_bounds__(512, 1) void edge_kernel(
    const float* __restrict__ dist, const int* __restrict__ ei,
    const float* __restrict__ fw1, const float* __restrict__ fb1,
    const float* __restrict__ fw2, const float* __restrict__ fb2)
{
    extern __shared__ float sm[];
    float* w1_s = sm;                      // 50*128
    float* w2_s = w1_s + 50 * 128;         // 128*128
    float* df_s = w2_s + 128 * 128;        // 128*52
    float* m_s  = df_s + 128 * 52;         // 128*132

    const int tid = threadIdx.x;
    const int tx = tid & 15, ty = tid >> 4;
    const int j0 = tx * 8, r0 = ty * 4;

    for (int i = tid; i < 50 * 128; i += 512) w1_s[i] = fw1[i];
    for (int i = tid; i < 128 * 128; i += 512) w2_s[i] = fw2[i];

    const float4 b1A = *(const float4*)(fb1 + j0);
    const float4 b1B = *(const float4*)(fb1 + j0 + 4);
    const float4 b2A = *(const float4*)(fb2 + j0);
    const float4 b2B = *(const float4*)(fb2 + j0 + 4);
    __syncthreads();

    const int n_tiles = N_EDGES / 128;   // 5000
    #pragma unroll 1
    for (int t = blockIdx.x; t < n_tiles; t += gridDim.x) {
        const int e0 = t * 128;
        __syncthreads();   // previous iteration fully done with df_s / m_s

        for (int i = tid; i < 128 * NG; i += 512) {
            const int r = i / NG, c = i - r * NG;
            df_s[r * 52 + c] = dist[(size_t)e0 * NG + i];
        }
        __syncthreads();

        float acc[4][8];
        gemm_tile<NG, 52>(df_s, w1_s, r0, j0, acc);

        #pragma unroll
        for (int i = 0; i < 4; i++) {
            float4 v0, v1;
            v0.x = silu_f(acc[i][0] + b1A.x); v0.y = silu_f(acc[i][1] + b1A.y);
            v0.z = silu_f(acc[i][2] + b1A.z); v0.w = silu_f(acc[i][3] + b1A.w);
            v1.x = silu_f(acc[i][4] + b1B.x); v1.y = silu_f(acc[i][5] + b1B.y);
            v1.z = silu_f(acc[i][6] + b1B.z); v1.w = silu_f(acc[i][7] + b1B.w);
            *(float4*)(m_s + (r0 + i) * 132 + j0) = v0;
            *(float4*)(m_s + (r0 + i) * 132 + j0 + 4) = v1;
        }
        __syncthreads();

        gemm_tile<128, 132>(m_s, w2_s, r0, j0, acc);

        #pragma unroll
        for (int i = 0; i < 4; i++) {
            const int e = e0 + r0 + i;
            const int s = ei[e];             // int32 edge_index row 0 (src)
            const int d = ei[N_EDGES + e];   // int32 edge_index row 1 (dst)
            const float4 x0 = *(const float4*)(g_x + s * 128 + j0);
            const float4 x1 = *(const float4*)(g_x + s * 128 + j0 + 4);
            float* dstp = g_agg + d * 128 + j0;
            float4 m0, m1;
            m0.x = (acc[i][0] + b2A.x) * x0.x; m0.y = (acc[i][1] + b2A.y) * x0.y;
            m0.z = (acc[i][2] + b2A.z) * x0.z; m0.w = (acc[i][3] + b2A.w) * x0.w;
            m1.x = (acc[i][4] + b2B.x) * x1.x; m1.y = (acc[i][5] + b2B.y) * x1.y;
            m1.z = (acc[i][6] + b2B.z) * x1.z; m1.w = (acc[i][7] + b2B.w) * x1.w;
            atomicAdd((float4*)dstp, m0);
            atomicAdd((float4*)(dstp + 4), m1);
        }
    }
}

extern "C" void kernel_launch(void* const* d_in, const int* in_sizes, int n_in,
                              void* d_out, int out_size)
{
    (void)in_sizes; (void)n_in; (void)out_size;
    const float* h    = (const float*)d_in[0];
    const int*   ei   = (const int*)d_in[1];     // int32 (JAX default x64-disabled)
    const float* dist = (const float*)d_in[2];
    const float* fw1  = (const float*)d_in[3];
    const float* fb1  = (const float*)d_in[4];
    const float* fw2  = (const float*)d_in[5];
    const float* fb2  = (const float*)d_in[6];
    const float* aw1  = (const float*)d_in[7];
    const float* ab1  = (const float*)d_in[8];
    const float* aw2  = (const float*)d_in[9];
    const float* ab2  = (const float*)d_in[10];
    const float* ow1  = (const float*)d_in[11];
    const float* ob1  = (const float*)d_in[12];
    const float* ow2  = (const float*)d_in[13];
    const float* ob2  = (const float*)d_in[14];
    float* out = (float*)d_out;

    const int NODE_SMEM = (128 * 128 + 2 * 64 * 132) * 4;                       // 133120 B
    const int EDGE_SMEM = (50 * 128 + 128 * 128 + 128 * 52 + 128 * 132) * 4;    // 185344 B

    cudaFuncSetAttribute(node_mlp_kernel, cudaFuncAttributeMaxDynamicSharedMemorySize, NODE_SMEM);
    cudaFuncSetAttribute(edge_kernel,     cudaFuncAttributeMaxDynamicSharedMemorySize, EDGE_SMEM);

    // 1) atom_net: g_x = silu(h@aw1+ab1)@aw2+ab2 ; also zero g_agg
    node_mlp_kernel<<<N_NODES / 64, 256, NODE_SMEM>>>(0, h, aw1, ab1, aw2, ab2, nullptr, nullptr);
    // 2) filter_net + gather-multiply-scatter into g_agg
    edge_kernel<<<148, 512, EDGE_SMEM>>>(dist, ei, fw1, fb1, fw2, fb2);
    // 3) output_net + residual: out = h + silu(g_agg@ow1+ob1)@ow2+ob2
    node_mlp_kernel<<<N_NODES / 64, 256, NODE_SMEM>>>(1, nullptr, ow1, ob1, ow2, ob2, out, h);
}